// round 3
// baseline (speedup 1.0000x reference)
#include <cuda_runtime.h>
#include <cstdint>

#define IMG_H 512
#define IMG_W 512
#define TILE_W 64
#define TILE_H 32
#define HALO 5
#define IN_W (TILE_W + 2*HALO)   // 74
#define IN_H (TILE_H + 2*HALO)   // 42
#define SSTRIDE 80               // padded row stride (floats), float4-friendly
#define NTHREADS 256

// Normalized Gaussian taps: g[k] = exp(-(k - 11/2)^2 / (2*1.5^2)) / sum, k=0..10.
// Center at 5.5 (matches reference) => ASYMMETRIC array: w[k] == w[11-k] for k>=1,
// w[0] is the unique smallest tap. Values computed offline in double precision.
__host__ __device__ __forceinline__ constexpr float Wc(int k) {
    return (k == 0)            ? 3.2030000e-04f
         : (k == 1 || k == 10) ? 2.9556400e-03f
         : (k == 2 || k == 9 ) ? 1.7487660e-02f
         : (k == 3 || k == 8 ) ? 6.6342400e-02f
         : (k == 4 || k == 7 ) ? 1.6137290e-01f
         :                       2.5168140e-01f;   // k == 5 || k == 6
}

// ---------------- global min/max of img1 -> C1, C2 ----------------

__device__ unsigned g_minmax[2];   // [0]=min (encoded), [1]=max (encoded)
__device__ float    g_C[2];        // [0]=C1, [1]=C2

__device__ __forceinline__ unsigned enc_f(float f) {
    unsigned u = __float_as_uint(f);
    return (u & 0x80000000u) ? ~u : (u | 0x80000000u);
}
__device__ __forceinline__ float dec_f(unsigned u) {
    return (u & 0x80000000u) ? __uint_as_float(u ^ 0x80000000u) : __uint_as_float(~u);
}

__global__ void init_minmax_k() {
    g_minmax[0] = 0xFFFFFFFFu;  // encoded min start
    g_minmax[1] = 0u;           // encoded max start
}

__global__ void minmax_k(const float4* __restrict__ x, int n4) {
    float lo =  3.402823466e38f;
    float hi = -3.402823466e38f;
    for (int i = blockIdx.x * blockDim.x + threadIdx.x; i < n4; i += gridDim.x * blockDim.x) {
        float4 v = x[i];
        lo = fminf(lo, fminf(fminf(v.x, v.y), fminf(v.z, v.w)));
        hi = fmaxf(hi, fmaxf(fmaxf(v.x, v.y), fmaxf(v.z, v.w)));
    }
    #pragma unroll
    for (int s = 16; s > 0; s >>= 1) {
        lo = fminf(lo, __shfl_xor_sync(0xFFFFFFFFu, lo, s));
        hi = fmaxf(hi, __shfl_xor_sync(0xFFFFFFFFu, hi, s));
    }
    __shared__ float slo[8], shi[8];
    int w = threadIdx.x >> 5, l = threadIdx.x & 31;
    if (l == 0) { slo[w] = lo; shi[w] = hi; }
    __syncthreads();
    if (threadIdx.x == 0) {
        int nw = blockDim.x >> 5;
        for (int i = 1; i < nw; i++) { lo = fminf(lo, slo[i]); hi = fmaxf(hi, shi[i]); }
        atomicMin(&g_minmax[0], enc_f(lo));
        atomicMax(&g_minmax[1], enc_f(hi));
    }
}

__global__ void finalize_k() {
    float mn = dec_f(g_minmax[0]);
    float mx = dec_f(g_minmax[1]);
    float L = mx - mn;
    if (L == 0.0f) L = 5.0f;
    float c1 = 0.01f * L, c2 = 0.03f * L;
    g_C[0] = c1 * c1;
    g_C[1] = c2 * c2;
}

// ---------------- fused separable SSIM kernel ----------------
//
// One block = 64x32 output tile of one batch image.
// Phase 1: cooperative load of 74x42 halo tiles of img1/img2 into smem.
// Phase 2: vertical 11-tap conv (5 fields), 4-row register blocking, into smem mid.
// Phase 3: horizontal 11-tap conv via float4 smem loads, 8-wide per thread, + SSIM formula.

__global__ void __launch_bounds__(NTHREADS, 2)
ssim_kernel(const float* __restrict__ img1, const float* __restrict__ img2,
            float* __restrict__ out)
{
    extern __shared__ float smem[];
    float* s1  = smem;                      // IN_H * SSTRIDE
    float* s2  = smem + IN_H * SSTRIDE;     // IN_H * SSTRIDE
    float* mid = smem + 2 * IN_H * SSTRIDE; // 5 * TILE_H * SSTRIDE

    const int bx = blockIdx.x, by = blockIdx.y, bz = blockIdx.z;
    const int tid = threadIdx.x;
    const size_t base = (size_t)bz * (IMG_H * IMG_W);
    const float* p1 = img1 + base;
    const float* p2 = img2 + base;

    // ---- Phase 1: load halo tiles (zero padding at borders) ----
    for (int idx = tid; idx < IN_H * IN_W; idx += NTHREADS) {
        int r = idx / IN_W;
        int c = idx - r * IN_W;
        int gy = by * TILE_H + r - HALO;
        int gx = bx * TILE_W + c - HALO;
        float v1 = 0.0f, v2 = 0.0f;
        if ((unsigned)gy < (unsigned)IMG_H && (unsigned)gx < (unsigned)IMG_W) {
            int o = gy * IMG_W + gx;
            v1 = __ldg(p1 + o);
            v2 = __ldg(p2 + o);
        }
        s1[r * SSTRIDE + c] = v1;
        s2[r * SSTRIDE + c] = v2;
    }
    __syncthreads();

    // ---- Phase 2: vertical conv, 4 output rows per task ----
    for (int task = tid; task < IN_W * (TILE_H / 4); task += NTHREADS) {
        int c  = task % IN_W;
        int j0 = (task / IN_W) * 4;
        float a[14], b[14], xx[14], yy[14], xy[14];
        #pragma unroll
        for (int r = 0; r < 14; r++) {
            float x = s1[(j0 + r) * SSTRIDE + c];
            float y = s2[(j0 + r) * SSTRIDE + c];
            a[r] = x; b[r] = y;
            xx[r] = x * x; yy[r] = y * y; xy[r] = x * y;
        }
        #pragma unroll
        for (int m = 0; m < 4; m++) {
            float A0 = 0.f, A1 = 0.f, A2 = 0.f, A3 = 0.f, A4 = 0.f;
            #pragma unroll
            for (int k = 0; k < 11; k++) {
                const float w = Wc(k);
                A0 = fmaf(w, a[m + k], A0);
                A1 = fmaf(w, b[m + k], A1);
                A2 = fmaf(w, xx[m + k], A2);
                A3 = fmaf(w, yy[m + k], A3);
                A4 = fmaf(w, xy[m + k], A4);
            }
            int o = (j0 + m) * SSTRIDE + c;
            mid[0 * TILE_H * SSTRIDE + o] = A0;
            mid[1 * TILE_H * SSTRIDE + o] = A1;
            mid[2 * TILE_H * SSTRIDE + o] = A2;
            mid[3 * TILE_H * SSTRIDE + o] = A3;
            mid[4 * TILE_H * SSTRIDE + o] = A4;
        }
    }
    __syncthreads();

    // ---- Phase 3: horizontal conv (8 outputs per thread) + SSIM formula ----
    const int row = tid >> 3;          // 0..31
    const int c0  = (tid & 7) * 8;     // 0,8,...,56 (mid col base; output col base too)

    float res[5][8];
    #pragma unroll
    for (int f = 0; f < 5; f++) {
        float t[20];
        const float4* p = reinterpret_cast<const float4*>(
            mid + f * TILE_H * SSTRIDE + row * SSTRIDE + c0);
        #pragma unroll
        for (int q = 0; q < 5; q++) {
            float4 u = p[q];
            t[4*q+0] = u.x; t[4*q+1] = u.y; t[4*q+2] = u.z; t[4*q+3] = u.w;
        }
        #pragma unroll
        for (int i = 0; i < 8; i++) {
            float acc = 0.f;
            #pragma unroll
            for (int k = 0; k < 11; k++)
                acc = fmaf(Wc(k), t[i + k], acc);
            res[f][i] = acc;
        }
    }

    const float C1 = g_C[0];
    const float C2 = g_C[1];
    float o8[8];
    #pragma unroll
    for (int i = 0; i < 8; i++) {
        float mu1 = res[0][i], mu2 = res[1][i];
        float mu1s = mu1 * mu1, mu2s = mu2 * mu2, m12 = mu1 * mu2;
        float s1q = res[2][i] - mu1s;
        float s2q = res[3][i] - mu2s;
        float s12 = res[4][i] - m12;
        float num = (2.f * m12 + C1) * (2.f * s12 + C2);
        float den = (mu1s + mu2s + C1) * (s1q + s2q + C2);
        o8[i] = __fdividef(num, den);
    }

    const int gy = by * TILE_H + row;
    const int gx = bx * TILE_W + c0;
    float4* po = reinterpret_cast<float4*>(out + base + gy * IMG_W + gx);
    po[0] = make_float4(o8[0], o8[1], o8[2], o8[3]);
    po[1] = make_float4(o8[4], o8[5], o8[6], o8[7]);
}

// ---------------- launch ----------------

extern "C" void kernel_launch(void* const* d_in, const int* in_sizes, int n_in,
                              void* d_out, int out_size)
{
    const float* img1 = (const float*)d_in[0];
    const float* img2 = (const float*)d_in[1];
    float* out = (float*)d_out;
    const int n = in_sizes[0];
    const int batch = n / (IMG_H * IMG_W);

    const int smem_bytes = (2 * IN_H * SSTRIDE + 5 * TILE_H * SSTRIDE) * (int)sizeof(float);
    cudaFuncSetAttribute(ssim_kernel, cudaFuncAttributeMaxDynamicSharedMemorySize, smem_bytes);

    init_minmax_k<<<1, 1>>>();
    minmax_k<<<1184, 256>>>((const float4*)img1, n / 4);
    finalize_k<<<1, 1>>>();

    dim3 grid(IMG_W / TILE_W, IMG_H / TILE_H, batch);
    ssim_kernel<<<grid, NTHREADS, smem_bytes>>>(img1, img2, out);
}

// round 4
// speedup vs baseline: 1.3718x; 1.3718x over previous
#include <cuda_runtime.h>
#include <cstdint>

#define IMG_H 512
#define IMG_W 512
#define TILE_W 64
#define TILE_H 16
#define HALO 5
#define IN_W (TILE_W + 2*HALO)   // 74
#define IN_H (TILE_H + 2*HALO)   // 26
#define SSTRIDE 80               // padded row stride (floats), float4-friendly
#define NTHREADS 256

// Normalized Gaussian taps: g[k] = exp(-(k - 11/2)^2 / (2*1.5^2)) / sum, k=0..10.
// Center at 5.5 (matches reference) => ASYMMETRIC: w[k] == w[11-k] for k>=1,
// w[0] unique smallest. Computed offline in double precision.
__host__ __device__ __forceinline__ constexpr float Wc(int k) {
    return (k == 0)            ? 3.2030000e-04f
         : (k == 1 || k == 10) ? 2.9556400e-03f
         : (k == 2 || k == 9 ) ? 1.7487660e-02f
         : (k == 3 || k == 8 ) ? 6.6342400e-02f
         : (k == 4 || k == 7 ) ? 1.6137290e-01f
         :                       2.5168140e-01f;   // k == 5 || k == 6
}

// ---------------- global min/max of img1 -> C1, C2 ----------------

__device__ unsigned g_minmax[2];
__device__ float    g_C[2];        // [0]=C1, [1]=C2

__device__ __forceinline__ unsigned enc_f(float f) {
    unsigned u = __float_as_uint(f);
    return (u & 0x80000000u) ? ~u : (u | 0x80000000u);
}
__device__ __forceinline__ float dec_f(unsigned u) {
    return (u & 0x80000000u) ? __uint_as_float(u ^ 0x80000000u) : __uint_as_float(~u);
}

__global__ void init_minmax_k() {
    g_minmax[0] = 0xFFFFFFFFu;
    g_minmax[1] = 0u;
}

__global__ void minmax_k(const float4* __restrict__ x, int n4) {
    float lo =  3.402823466e38f;
    float hi = -3.402823466e38f;
    for (int i = blockIdx.x * blockDim.x + threadIdx.x; i < n4; i += gridDim.x * blockDim.x) {
        float4 v = x[i];
        lo = fminf(lo, fminf(fminf(v.x, v.y), fminf(v.z, v.w)));
        hi = fmaxf(hi, fmaxf(fmaxf(v.x, v.y), fmaxf(v.z, v.w)));
    }
    #pragma unroll
    for (int s = 16; s > 0; s >>= 1) {
        lo = fminf(lo, __shfl_xor_sync(0xFFFFFFFFu, lo, s));
        hi = fmaxf(hi, __shfl_xor_sync(0xFFFFFFFFu, hi, s));
    }
    __shared__ float slo[8], shi[8];
    int w = threadIdx.x >> 5, l = threadIdx.x & 31;
    if (l == 0) { slo[w] = lo; shi[w] = hi; }
    __syncthreads();
    if (threadIdx.x == 0) {
        int nw = blockDim.x >> 5;
        for (int i = 1; i < nw; i++) { lo = fminf(lo, slo[i]); hi = fmaxf(hi, shi[i]); }
        atomicMin(&g_minmax[0], enc_f(lo));
        atomicMax(&g_minmax[1], enc_f(hi));
    }
}

__global__ void finalize_k() {
    float mn = dec_f(g_minmax[0]);
    float mx = dec_f(g_minmax[1]);
    float L = mx - mn;
    if (L == 0.0f) L = 5.0f;
    float c1 = 0.01f * L, c2 = 0.03f * L;
    g_C[0] = c1 * c1;
    g_C[1] = c2 * c2;
}

// ---------------- fused separable SSIM kernel ----------------
//
// One block = 64x16 output tile. smem = 42.2KB -> 5 blocks/SM (62.5% occ).
// Phase 1: load 74x26 halo tiles of img1/img2 into smem.
// Phase 2: vertical 11-tap conv (5 fields) with on-the-fly products
//          (low register pressure), 4-row blocking, into smem mid.
// Phase 3: horizontal 11-tap conv via float4 smem loads, 4 outputs/thread,
//          + SSIM formula, float4 store.

__global__ void __launch_bounds__(NTHREADS, 5)
ssim_kernel(const float* __restrict__ img1, const float* __restrict__ img2,
            float* __restrict__ out)
{
    extern __shared__ float smem[];
    float* s1  = smem;                      // IN_H * SSTRIDE
    float* s2  = smem + IN_H * SSTRIDE;
    float* mid = smem + 2 * IN_H * SSTRIDE; // 5 * TILE_H * SSTRIDE

    const int bx = blockIdx.x, by = blockIdx.y, bz = blockIdx.z;
    const int tid = threadIdx.x;
    const size_t base = (size_t)bz * (IMG_H * IMG_W);
    const float* p1 = img1 + base;
    const float* p2 = img2 + base;

    // ---- Phase 1: load halo tiles (zero padding at borders) ----
    for (int idx = tid; idx < IN_H * IN_W; idx += NTHREADS) {
        int r = idx / IN_W;
        int c = idx - r * IN_W;
        int gy = by * TILE_H + r - HALO;
        int gx = bx * TILE_W + c - HALO;
        float v1 = 0.0f, v2 = 0.0f;
        if ((unsigned)gy < (unsigned)IMG_H && (unsigned)gx < (unsigned)IMG_W) {
            int o = gy * IMG_W + gx;
            v1 = __ldg(p1 + o);
            v2 = __ldg(p2 + o);
        }
        s1[r * SSTRIDE + c] = v1;
        s2[r * SSTRIDE + c] = v2;
    }
    __syncthreads();

    // ---- Phase 2: vertical conv, 4 output rows per task, products on the fly ----
    for (int task = tid; task < IN_W * (TILE_H / 4); task += NTHREADS) {
        int c  = task % IN_W;
        int j0 = (task / IN_W) * 4;
        float a[14], b[14];
        #pragma unroll
        for (int r = 0; r < 14; r++) {
            a[r] = s1[(j0 + r) * SSTRIDE + c];
            b[r] = s2[(j0 + r) * SSTRIDE + c];
        }
        #pragma unroll
        for (int m = 0; m < 4; m++) {
            float A0 = 0.f, A1 = 0.f, A2 = 0.f, A3 = 0.f, A4 = 0.f;
            #pragma unroll
            for (int k = 0; k < 11; k++) {
                const float w = Wc(k);
                float x = a[m + k], y = b[m + k];
                float wx = w * x, wy = w * y;
                A0 += wx;
                A1 += wy;
                A2 = fmaf(wx, x, A2);
                A3 = fmaf(wy, y, A3);
                A4 = fmaf(wx, y, A4);
            }
            int o = (j0 + m) * SSTRIDE + c;
            mid[0 * TILE_H * SSTRIDE + o] = A0;
            mid[1 * TILE_H * SSTRIDE + o] = A1;
            mid[2 * TILE_H * SSTRIDE + o] = A2;
            mid[3 * TILE_H * SSTRIDE + o] = A3;
            mid[4 * TILE_H * SSTRIDE + o] = A4;
        }
    }
    __syncthreads();

    // ---- Phase 3: horizontal conv (4 outputs per thread) + SSIM formula ----
    const int row = tid >> 4;          // 0..15
    const int c0  = (tid & 15) * 4;    // 0,4,...,60

    float res[5][4];
    #pragma unroll
    for (int f = 0; f < 5; f++) {
        float t[16];
        const float4* p = reinterpret_cast<const float4*>(
            mid + f * TILE_H * SSTRIDE + row * SSTRIDE + c0);
        #pragma unroll
        for (int q = 0; q < 4; q++) {
            float4 u = p[q];
            t[4*q+0] = u.x; t[4*q+1] = u.y; t[4*q+2] = u.z; t[4*q+3] = u.w;
        }
        #pragma unroll
        for (int i = 0; i < 4; i++) {
            float acc = 0.f;
            #pragma unroll
            for (int k = 0; k < 11; k++)
                acc = fmaf(Wc(k), t[i + k], acc);
            res[f][i] = acc;
        }
    }

    const float C1 = g_C[0];
    const float C2 = g_C[1];
    float o4[4];
    #pragma unroll
    for (int i = 0; i < 4; i++) {
        float mu1 = res[0][i], mu2 = res[1][i];
        float mu1s = mu1 * mu1, mu2s = mu2 * mu2, m12 = mu1 * mu2;
        float s1q = res[2][i] - mu1s;
        float s2q = res[3][i] - mu2s;
        float s12 = res[4][i] - m12;
        float num = (2.f * m12 + C1) * (2.f * s12 + C2);
        float den = (mu1s + mu2s + C1) * (s1q + s2q + C2);
        o4[i] = __fdividef(num, den);
    }

    const int gy = by * TILE_H + row;
    const int gx = bx * TILE_W + c0;
    float4* po = reinterpret_cast<float4*>(out + base + gy * IMG_W + gx);
    po[0] = make_float4(o4[0], o4[1], o4[2], o4[3]);
}

// ---------------- launch ----------------

extern "C" void kernel_launch(void* const* d_in, const int* in_sizes, int n_in,
                              void* d_out, int out_size)
{
    const float* img1 = (const float*)d_in[0];
    const float* img2 = (const float*)d_in[1];
    float* out = (float*)d_out;
    const int n = in_sizes[0];
    const int batch = n / (IMG_H * IMG_W);

    const int smem_bytes = (2 * IN_H * SSTRIDE + 5 * TILE_H * SSTRIDE) * (int)sizeof(float);
    cudaFuncSetAttribute(ssim_kernel, cudaFuncAttributeMaxDynamicSharedMemorySize, smem_bytes);

    init_minmax_k<<<1, 1>>>();
    minmax_k<<<1184, 256>>>((const float4*)img1, n / 4);
    finalize_k<<<1, 1>>>();

    dim3 grid(IMG_W / TILE_W, IMG_H / TILE_H, batch);
    ssim_kernel<<<grid, NTHREADS, smem_bytes>>>(img1, img2, out);
}

// round 5
// speedup vs baseline: 1.7469x; 1.2734x over previous
#include <cuda_runtime.h>
#include <cstdint>

#define IMG_H 512
#define IMG_W 512
#define TILE_W 64
#define TILE_H 16
#define HALO 5
#define IN_W (TILE_W + 2*HALO)   // 74 logical halo columns
#define IN_H (TILE_H + 2*HALO)   // 26
#define SSTRIDE 80               // padded smem row stride (floats)
#define NTHREADS 256

// Normalized Gaussian taps: g[k] = exp(-(k - 11/2)^2 / (2*1.5^2)) / sum, k=0..10.
// Center at 5.5 => ASYMMETRIC: w[k] == w[11-k] for k>=1, w[0] unique smallest.
__host__ __device__ __forceinline__ constexpr float Wc(int k) {
    return (k == 0)            ? 3.2030000e-04f
         : (k == 1 || k == 10) ? 2.9556400e-03f
         : (k == 2 || k == 9 ) ? 1.7487660e-02f
         : (k == 3 || k == 8 ) ? 6.6342400e-02f
         : (k == 4 || k == 7 ) ? 1.6137290e-01f
         :                       2.5168140e-01f;   // k == 5 || k == 6
}

// ---------------- global min/max of img1 -> C1, C2 ----------------

__device__ unsigned g_minmax[2];
__device__ float    g_C[2];        // [0]=C1, [1]=C2

__device__ __forceinline__ unsigned enc_f(float f) {
    unsigned u = __float_as_uint(f);
    return (u & 0x80000000u) ? ~u : (u | 0x80000000u);
}
__device__ __forceinline__ float dec_f(unsigned u) {
    return (u & 0x80000000u) ? __uint_as_float(u ^ 0x80000000u) : __uint_as_float(~u);
}

__global__ void init_minmax_k() {
    g_minmax[0] = 0xFFFFFFFFu;
    g_minmax[1] = 0u;
}

__global__ void minmax_k(const float4* __restrict__ x, int n4) {
    float lo =  3.402823466e38f;
    float hi = -3.402823466e38f;
    for (int i = blockIdx.x * blockDim.x + threadIdx.x; i < n4; i += gridDim.x * blockDim.x) {
        float4 v = x[i];
        lo = fminf(lo, fminf(fminf(v.x, v.y), fminf(v.z, v.w)));
        hi = fmaxf(hi, fmaxf(fmaxf(v.x, v.y), fmaxf(v.z, v.w)));
    }
    #pragma unroll
    for (int s = 16; s > 0; s >>= 1) {
        lo = fminf(lo, __shfl_xor_sync(0xFFFFFFFFu, lo, s));
        hi = fmaxf(hi, __shfl_xor_sync(0xFFFFFFFFu, hi, s));
    }
    __shared__ float slo[8], shi[8];
    int w = threadIdx.x >> 5, l = threadIdx.x & 31;
    if (l == 0) { slo[w] = lo; shi[w] = hi; }
    __syncthreads();
    if (threadIdx.x == 0) {
        int nw = blockDim.x >> 5;
        for (int i = 1; i < nw; i++) { lo = fminf(lo, slo[i]); hi = fmaxf(hi, shi[i]); }
        atomicMin(&g_minmax[0], enc_f(lo));
        atomicMax(&g_minmax[1], enc_f(hi));
    }
}

__global__ void finalize_k() {
    float mn = dec_f(g_minmax[0]);
    float mx = dec_f(g_minmax[1]);
    float L = mx - mn;
    if (L == 0.0f) L = 5.0f;
    float c1 = 0.01f * L, c2 = 0.03f * L;
    g_C[0] = c1 * c1;
    g_C[1] = c2 * c2;
}

// ---------------- fused separable SSIM kernel ----------------
//
// One block = 64x16 output tile. smem = 42.2KB -> 5 blocks/SM.
// Phase 1: float4 global loads into 80-wide smem rows (logical col c at smem col c+3).
// Phase 2: vertical 11-tap conv, products-once + imm-FFMA scatter, 4-row blocking.
// Phase 3: horizontal 11-tap conv via float4 smem loads + SSIM formula.

__global__ void __launch_bounds__(NTHREADS, 5)
ssim_kernel(const float* __restrict__ img1, const float* __restrict__ img2,
            float* __restrict__ out)
{
    extern __shared__ float smem[];
    float* s1  = smem;                      // IN_H * SSTRIDE
    float* s2  = smem + IN_H * SSTRIDE;
    float* mid = smem + 2 * IN_H * SSTRIDE; // 5 * TILE_H * SSTRIDE

    const int bx = blockIdx.x, by = blockIdx.y, bz = blockIdx.z;
    const int tid = threadIdx.x;
    const size_t base = (size_t)bz * (IMG_H * IMG_W);
    const float* p1 = img1 + base;
    const float* p2 = img2 + base;

    // ---- Phase 1: vectorized halo load (80 cols: gx in [bx*64-8, bx*64+72)) ----
    const int gx_base = bx * TILE_W - 8;   // 16B-aligned
    for (int idx = tid; idx < IN_H * 20; idx += NTHREADS) {
        int r = idx / 20;
        int c4 = idx - r * 20;
        int gy = by * TILE_H + r - HALO;
        int gx = gx_base + c4 * 4;
        float4 v1 = make_float4(0.f, 0.f, 0.f, 0.f);
        float4 v2 = v1;
        if ((unsigned)gy < (unsigned)IMG_H) {
            const float* r1 = p1 + gy * IMG_W;
            const float* r2 = p2 + gy * IMG_W;
            if (gx >= 0 && gx + 3 < IMG_W) {
                v1 = *reinterpret_cast<const float4*>(r1 + gx);
                v2 = *reinterpret_cast<const float4*>(r2 + gx);
            } else {
                float* a1 = reinterpret_cast<float*>(&v1);
                float* a2 = reinterpret_cast<float*>(&v2);
                #pragma unroll
                for (int j = 0; j < 4; j++) {
                    int g = gx + j;
                    if ((unsigned)g < (unsigned)IMG_W) {
                        a1[j] = __ldg(r1 + g);
                        a2[j] = __ldg(r2 + g);
                    }
                }
            }
        }
        *reinterpret_cast<float4*>(s1 + r * SSTRIDE + c4 * 4) = v1;
        *reinterpret_cast<float4*>(s2 + r * SSTRIDE + c4 * 4) = v2;
    }
    __syncthreads();

    // ---- Phase 2: vertical conv, products-once + imm-FFMA scatter ----
    for (int task = tid; task < IN_W * (TILE_H / 4); task += NTHREADS) {
        int c  = task % IN_W;              // logical column 0..73
        int j0 = (task / IN_W) * 4;
        const float* col1 = s1 + j0 * SSTRIDE + (c + 3);
        const float* col2 = s2 + j0 * SSTRIDE + (c + 3);

        float A[4][5];
        #pragma unroll
        for (int m = 0; m < 4; m++)
            #pragma unroll
            for (int f = 0; f < 5; f++)
                A[m][f] = 0.f;

        #pragma unroll
        for (int r = 0; r < 14; r++) {
            float x = col1[r * SSTRIDE];
            float y = col2[r * SSTRIDE];
            float xx = x * x, yy = y * y, xy = x * y;
            #pragma unroll
            for (int m = 0; m < 4; m++) {
                const int k = r - m;
                if (k >= 0 && k < 11) {      // compile-time resolved
                    const float w = Wc(k);   // literal -> imm-form FFMA
                    A[m][0] = fmaf(x,  w, A[m][0]);
                    A[m][1] = fmaf(y,  w, A[m][1]);
                    A[m][2] = fmaf(xx, w, A[m][2]);
                    A[m][3] = fmaf(yy, w, A[m][3]);
                    A[m][4] = fmaf(xy, w, A[m][4]);
                }
            }
        }
        #pragma unroll
        for (int m = 0; m < 4; m++) {
            int o = (j0 + m) * SSTRIDE + c;
            #pragma unroll
            for (int f = 0; f < 5; f++)
                mid[f * TILE_H * SSTRIDE + o] = A[m][f];
        }
    }
    __syncthreads();

    // ---- Phase 3: horizontal conv (4 outputs per thread) + SSIM formula ----
    const int row = tid >> 4;          // 0..15
    const int c0  = (tid & 15) * 4;    // 0,4,...,60

    float res[5][4];
    #pragma unroll
    for (int f = 0; f < 5; f++) {
        float t[16];
        const float4* p = reinterpret_cast<const float4*>(
            mid + f * TILE_H * SSTRIDE + row * SSTRIDE + c0);
        #pragma unroll
        for (int q = 0; q < 4; q++) {
            float4 u = p[q];
            t[4*q+0] = u.x; t[4*q+1] = u.y; t[4*q+2] = u.z; t[4*q+3] = u.w;
        }
        #pragma unroll
        for (int i = 0; i < 4; i++) {
            float acc = 0.f;
            #pragma unroll
            for (int k = 0; k < 11; k++)
                acc = fmaf(t[i + k], Wc(k), acc);
            res[f][i] = acc;
        }
    }

    const float C1 = g_C[0];
    const float C2 = g_C[1];
    float o4[4];
    #pragma unroll
    for (int i = 0; i < 4; i++) {
        float mu1 = res[0][i], mu2 = res[1][i];
        float mu1s = mu1 * mu1, mu2s = mu2 * mu2, m12 = mu1 * mu2;
        float s1q = res[2][i] - mu1s;
        float s2q = res[3][i] - mu2s;
        float s12 = res[4][i] - m12;
        float num = (2.f * m12 + C1) * (2.f * s12 + C2);
        float den = (mu1s + mu2s + C1) * (s1q + s2q + C2);
        o4[i] = __fdividef(num, den);
    }

    const int gy = by * TILE_H + row;
    const int gx = bx * TILE_W + c0;
    float4* po = reinterpret_cast<float4*>(out + base + gy * IMG_W + gx);
    po[0] = make_float4(o4[0], o4[1], o4[2], o4[3]);
}

// ---------------- launch ----------------

extern "C" void kernel_launch(void* const* d_in, const int* in_sizes, int n_in,
                              void* d_out, int out_size)
{
    const float* img1 = (const float*)d_in[0];
    const float* img2 = (const float*)d_in[1];
    float* out = (float*)d_out;
    const int n = in_sizes[0];
    const int batch = n / (IMG_H * IMG_W);

    const int smem_bytes = (2 * IN_H * SSTRIDE + 5 * TILE_H * SSTRIDE) * (int)sizeof(float);
    cudaFuncSetAttribute(ssim_kernel, cudaFuncAttributeMaxDynamicSharedMemorySize, smem_bytes);

    init_minmax_k<<<1, 1>>>();
    minmax_k<<<1184, 256>>>((const float4*)img1, n / 4);
    finalize_k<<<1, 1>>>();

    dim3 grid(IMG_W / TILE_W, IMG_H / TILE_H, batch);
    ssim_kernel<<<grid, NTHREADS, smem_bytes>>>(img1, img2, out);
}

// round 6
// speedup vs baseline: 2.1887x; 1.2529x over previous
#include <cuda_runtime.h>
#include <cstdint>

#define IMG_H 512
#define IMG_W 512
#define TILE_W 64
#define TILE_H 16
#define HALO 5
#define IN_W (TILE_W + 2*HALO)   // 74 logical halo columns
#define IN_H (TILE_H + 2*HALO)   // 26
#define SSTRIDE 80               // padded smem row stride (floats)
#define NTHREADS 256
#define NFIELDS 4                // mu1, mu2, xx+yy, xy

// Normalized Gaussian taps: g[k] = exp(-(k - 11/2)^2 / (2*1.5^2)) / sum, k=0..10.
// Center at 5.5 => ASYMMETRIC: w[k] == w[11-k] for k>=1, w[0] unique smallest.
__host__ __device__ __forceinline__ constexpr float Wc(int k) {
    return (k == 0)            ? 3.2030000e-04f
         : (k == 1 || k == 10) ? 2.9556400e-03f
         : (k == 2 || k == 9 ) ? 1.7487660e-02f
         : (k == 3 || k == 8 ) ? 6.6342400e-02f
         : (k == 4 || k == 7 ) ? 1.6137290e-01f
         :                       2.5168140e-01f;   // k == 5 || k == 6
}

// ---------------- global min/max of img1 ----------------

__device__ unsigned g_minmax[2];

__device__ __forceinline__ unsigned enc_f(float f) {
    unsigned u = __float_as_uint(f);
    return (u & 0x80000000u) ? ~u : (u | 0x80000000u);
}
__device__ __forceinline__ float dec_f(unsigned u) {
    return (u & 0x80000000u) ? __uint_as_float(u ^ 0x80000000u) : __uint_as_float(~u);
}

__global__ void init_minmax_k() {
    g_minmax[0] = 0xFFFFFFFFu;
    g_minmax[1] = 0u;
}

__global__ void minmax_k(const float4* __restrict__ x, int n4) {
    float lo =  3.402823466e38f;
    float hi = -3.402823466e38f;
    for (int i = blockIdx.x * blockDim.x + threadIdx.x; i < n4; i += gridDim.x * blockDim.x) {
        float4 v = x[i];
        lo = fminf(lo, fminf(fminf(v.x, v.y), fminf(v.z, v.w)));
        hi = fmaxf(hi, fmaxf(fmaxf(v.x, v.y), fmaxf(v.z, v.w)));
    }
    #pragma unroll
    for (int s = 16; s > 0; s >>= 1) {
        lo = fminf(lo, __shfl_xor_sync(0xFFFFFFFFu, lo, s));
        hi = fmaxf(hi, __shfl_xor_sync(0xFFFFFFFFu, hi, s));
    }
    __shared__ float slo[8], shi[8];
    int w = threadIdx.x >> 5, l = threadIdx.x & 31;
    if (l == 0) { slo[w] = lo; shi[w] = hi; }
    __syncthreads();
    if (threadIdx.x == 0) {
        int nw = blockDim.x >> 5;
        for (int i = 1; i < nw; i++) { lo = fminf(lo, slo[i]); hi = fmaxf(hi, shi[i]); }
        atomicMin(&g_minmax[0], enc_f(lo));
        atomicMax(&g_minmax[1], enc_f(hi));
    }
}

// ---------------- fused separable SSIM kernel ----------------
//
// One block = 64x16 output tile. smem = 37.1KB -> 6 blocks/SM (75% occ).
// Phase 1: cp.async 16B zfill loads (granules fully in/out of bounds by construction).
// Phase 2: vertical 11-tap conv of 4 fields (mu1, mu2, xx+yy, xy), imm-FFMA scatter.
// Phase 3: horizontal 11-tap conv via float4 smem loads + SSIM formula
//          (sigma1_sq+sigma2_sq = conv(xx+yy) - mu1^2 - mu2^2).

__global__ void __launch_bounds__(NTHREADS, 6)
ssim_kernel(const float* __restrict__ img1, const float* __restrict__ img2,
            float* __restrict__ out)
{
    extern __shared__ float smem[];
    float* s1  = smem;                      // IN_H * SSTRIDE
    float* s2  = smem + IN_H * SSTRIDE;
    float* mid = smem + 2 * IN_H * SSTRIDE; // NFIELDS * TILE_H * SSTRIDE

    const int bx = blockIdx.x, by = blockIdx.y, bz = blockIdx.z;
    const int tid = threadIdx.x;
    const size_t base = (size_t)bz * (IMG_H * IMG_W);
    const float* p1 = img1 + base;
    const float* p2 = img2 + base;

    // ---- Phase 1: cp.async halo load, zero-fill OOB granules ----
    const int gx_base = bx * TILE_W - 8;    // 16B-aligned; granules fully in/out
    const int gy_base = by * TILE_H - HALO;
    for (int idx = tid; idx < IN_H * 20; idx += NTHREADS) {
        int r  = idx / 20;
        int c4 = idx - r * 20;
        int gy = gy_base + r;
        int gx = gx_base + c4 * 4;
        bool ok = ((unsigned)gy < (unsigned)IMG_H) && ((unsigned)gx < (unsigned)IMG_W);
        int cgy = min(max(gy, 0), IMG_H - 1);      // clamp so address is always valid
        int cgx = min(max(gx, 0), IMG_W - 4);
        const float* g1 = p1 + cgy * IMG_W + cgx;
        const float* g2 = p2 + cgy * IMG_W + cgx;
        unsigned d1 = (unsigned)__cvta_generic_to_shared(s1 + r * SSTRIDE + c4 * 4);
        unsigned d2 = (unsigned)__cvta_generic_to_shared(s2 + r * SSTRIDE + c4 * 4);
        int sz = ok ? 16 : 0;
        asm volatile("cp.async.cg.shared.global [%0], [%1], 16, %2;\n"
                     :: "r"(d1), "l"(g1), "r"(sz));
        asm volatile("cp.async.cg.shared.global [%0], [%1], 16, %2;\n"
                     :: "r"(d2), "l"(g2), "r"(sz));
    }
    asm volatile("cp.async.commit_group;\n");
    asm volatile("cp.async.wait_group 0;\n");
    __syncthreads();

    // ---- Phase 2: vertical conv, products-once + imm-FFMA scatter ----
    for (int task = tid; task < IN_W * (TILE_H / 4); task += NTHREADS) {
        int c  = task % IN_W;              // logical column 0..73
        int j0 = (task / IN_W) * 4;
        const float* col1 = s1 + j0 * SSTRIDE + (c + 3);
        const float* col2 = s2 + j0 * SSTRIDE + (c + 3);

        float A[4][NFIELDS];
        #pragma unroll
        for (int m = 0; m < 4; m++)
            #pragma unroll
            for (int f = 0; f < NFIELDS; f++)
                A[m][f] = 0.f;

        #pragma unroll
        for (int r = 0; r < 14; r++) {
            float x = col1[r * SSTRIDE];
            float y = col2[r * SSTRIDE];
            float xy   = x * y;
            float xxyy = fmaf(x, x, y * y);
            #pragma unroll
            for (int m = 0; m < 4; m++) {
                const int k = r - m;
                if (k >= 0 && k < 11) {      // compile-time resolved
                    const float w = Wc(k);   // literal -> imm-form FFMA
                    A[m][0] = fmaf(x,    w, A[m][0]);
                    A[m][1] = fmaf(y,    w, A[m][1]);
                    A[m][2] = fmaf(xxyy, w, A[m][2]);
                    A[m][3] = fmaf(xy,   w, A[m][3]);
                }
            }
        }
        #pragma unroll
        for (int m = 0; m < 4; m++) {
            int o = (j0 + m) * SSTRIDE + c;
            #pragma unroll
            for (int f = 0; f < NFIELDS; f++)
                mid[f * TILE_H * SSTRIDE + o] = A[m][f];
        }
    }
    __syncthreads();

    // ---- Phase 3: horizontal conv (4 outputs per thread) + SSIM formula ----
    const int row = tid >> 4;          // 0..15
    const int c0  = (tid & 15) * 4;    // 0,4,...,60

    float res[NFIELDS][4];
    #pragma unroll
    for (int f = 0; f < NFIELDS; f++) {
        float t[16];
        const float4* p = reinterpret_cast<const float4*>(
            mid + f * TILE_H * SSTRIDE + row * SSTRIDE + c0);
        #pragma unroll
        for (int q = 0; q < 4; q++) {
            float4 u = p[q];
            t[4*q+0] = u.x; t[4*q+1] = u.y; t[4*q+2] = u.z; t[4*q+3] = u.w;
        }
        #pragma unroll
        for (int i = 0; i < 4; i++) {
            float acc = 0.f;
            #pragma unroll
            for (int k = 0; k < 11; k++)
                acc = fmaf(t[i + k], Wc(k), acc);
            res[f][i] = acc;
        }
    }

    // C1/C2 from global min/max (finalize merged here)
    float L = dec_f(g_minmax[1]) - dec_f(g_minmax[0]);
    if (L == 0.0f) L = 5.0f;
    const float c1v = 0.01f * L, c2v = 0.03f * L;
    const float C1 = c1v * c1v, C2 = c2v * c2v;

    float o4[4];
    #pragma unroll
    for (int i = 0; i < 4; i++) {
        float mu1 = res[0][i], mu2 = res[1][i];
        float mu1s = mu1 * mu1, mu2s = mu2 * mu2, m12 = mu1 * mu2;
        float sqsum = res[2][i] - mu1s - mu2s;   // sigma1_sq + sigma2_sq
        float s12   = res[3][i] - m12;           // sigma12
        float num = (2.f * m12 + C1) * (2.f * s12 + C2);
        float den = (mu1s + mu2s + C1) * (sqsum + C2);
        o4[i] = __fdividef(num, den);
    }

    const int gy = by * TILE_H + row;
    const int gx = bx * TILE_W + c0;
    float4* po = reinterpret_cast<float4*>(out + base + gy * IMG_W + gx);
    po[0] = make_float4(o4[0], o4[1], o4[2], o4[3]);
}

// ---------------- launch ----------------

extern "C" void kernel_launch(void* const* d_in, const int* in_sizes, int n_in,
                              void* d_out, int out_size)
{
    const float* img1 = (const float*)d_in[0];
    const float* img2 = (const float*)d_in[1];
    float* out = (float*)d_out;
    const int n = in_sizes[0];
    const int batch = n / (IMG_H * IMG_W);

    const int smem_bytes = (2 * IN_H * SSTRIDE + NFIELDS * TILE_H * SSTRIDE) * (int)sizeof(float);
    cudaFuncSetAttribute(ssim_kernel, cudaFuncAttributeMaxDynamicSharedMemorySize, smem_bytes);

    init_minmax_k<<<1, 1>>>();
    minmax_k<<<1184, 256>>>((const float4*)img1, n / 4);

    dim3 grid(IMG_W / TILE_W, IMG_H / TILE_H, batch);
    ssim_kernel<<<grid, NTHREADS, smem_bytes>>>(img1, img2, out);
}